// round 1
// baseline (speedup 1.0000x reference)
#include <cuda_runtime.h>
#include <cstdint>

// Problem constants
#define B_   16
#define NA_  2048
#define NB_  2048
#define D_   512
#define M_   (B_ * NA_)      // 32768 tokens
#define TOPK_ 4

// Scratch (device globals: allocation-free per harness rules)
__device__ float    g_Pa[M_ * D_];        // feats_a @ W2 + bias     (64 MB)
__device__ float    g_Pb[M_ * D_];        // feats_b @ (W1 - W2)     (64 MB)
__device__ float    g_Wd[D_ * D_];        // W1 - W2                 (1 MB)
__device__ unsigned g_topk[M_ * TOPK_];   // packed keys (sq<<11|idx)

// ---------------------------------------------------------------------------
// Kernel 1: Wd = W[0:512,:] - W[512:1024,:]   (elementwise over 262144 floats)
// ---------------------------------------------------------------------------
__global__ void prep_wd_kernel(const float* __restrict__ W) {
    int i = blockIdx.x * blockDim.x + threadIdx.x;   // float4 index, 65536 total
    float4 w1 = ((const float4*)W)[i];
    float4 w2 = ((const float4*)W)[i + 65536];
    float4 d;
    d.x = w1.x - w2.x; d.y = w1.y - w2.y; d.z = w1.z - w2.z; d.w = w1.w - w2.w;
    ((float4*)g_Wd)[i] = d;
}

// ---------------------------------------------------------------------------
// Kernel 2/3: SGEMM  C(M x 512) = A(M x 512) @ Bm(512 x 512) [+ bias]
// BM=128, BN=128, BK=8, 256 threads, 8x8 per-thread tile, double-buffered smem
// MODE 0: Bm = arg (W2), C = g_Pa, add bias.   MODE 1: Bm = g_Wd, C = g_Pb.
// ---------------------------------------------------------------------------
template <int MODE>
__global__ void __launch_bounds__(256, 2)
sgemm512_kernel(const float* __restrict__ A,
                const float* __restrict__ BmArg,
                const float* __restrict__ bias) {
    const int KD = 512, N = 512;
    const float* __restrict__ Bm = (MODE == 0) ? BmArg : g_Wd;
    float* __restrict__ C        = (MODE == 0) ? g_Pa  : g_Pb;

    __shared__ float As[2][8][128];
    __shared__ float Bs[2][8][128];

    const int tid = threadIdx.x;
    const int bm  = blockIdx.y;      // 0..255
    const int bn  = blockIdx.x;      // 0..3

    const float* Ab = A  + (size_t)bm * 128 * KD;
    const float* Bb = Bm + bn * 128;

    // load indices
    const int arow = tid >> 1;            // 0..127
    const int acol = (tid & 1) << 2;      // 0 or 4
    const int brow = tid >> 5;            // 0..7
    const int bcol = (tid & 31) << 2;     // 0..124

    const int tx = tid & 15;              // col group
    const int ty = tid >> 4;              // row group

    float acc[8][8];
#pragma unroll
    for (int i = 0; i < 8; ++i)
#pragma unroll
        for (int j = 0; j < 8; ++j) acc[i][j] = 0.0f;

    // prologue: load tile 0
    {
        float4 a = *(const float4*)(Ab + (size_t)arow * KD + acol);
        As[0][acol + 0][arow] = a.x;
        As[0][acol + 1][arow] = a.y;
        As[0][acol + 2][arow] = a.z;
        As[0][acol + 3][arow] = a.w;
        float4 b = *(const float4*)(Bb + (size_t)brow * N + bcol);
        *(float4*)&Bs[0][brow][bcol] = b;
    }
    __syncthreads();

    int buf = 0;
    for (int kt = 0; kt < 64; ++kt) {
        float4 a4, b4;
        const bool has_next = (kt < 63);
        if (has_next) {
            int k0 = (kt + 1) * 8;
            a4 = *(const float4*)(Ab + (size_t)arow * KD + k0 + acol);
            b4 = *(const float4*)(Bb + (size_t)(k0 + brow) * N + bcol);
        }
#pragma unroll
        for (int k = 0; k < 8; ++k) {
            float ra[8], rb[8];
            *(float4*)&ra[0] = *(const float4*)&As[buf][k][ty * 8];
            *(float4*)&ra[4] = *(const float4*)&As[buf][k][ty * 8 + 4];
            *(float4*)&rb[0] = *(const float4*)&Bs[buf][k][tx * 8];
            *(float4*)&rb[4] = *(const float4*)&Bs[buf][k][tx * 8 + 4];
#pragma unroll
            for (int i = 0; i < 8; ++i)
#pragma unroll
                for (int j = 0; j < 8; ++j)
                    acc[i][j] += ra[i] * rb[j];
        }
        if (has_next) {
            int nb = buf ^ 1;
            As[nb][acol + 0][arow] = a4.x;
            As[nb][acol + 1][arow] = a4.y;
            As[nb][acol + 2][arow] = a4.z;
            As[nb][acol + 3][arow] = a4.w;
            *(float4*)&Bs[nb][brow][bcol] = b4;
            __syncthreads();
            buf = nb;
        }
    }

    // epilogue
    const int ncol0 = bn * 128 + tx * 8;
    float bv[8];
#pragma unroll
    for (int j = 0; j < 8; ++j)
        bv[j] = (MODE == 0) ? bias[ncol0 + j] : 0.0f;

#pragma unroll
    for (int i = 0; i < 8; ++i) {
        size_t row = (size_t)bm * 128 + ty * 8 + i;
        float* cp = C + row * N + ncol0;
        float4 v0, v1;
        v0.x = acc[i][0] + bv[0]; v0.y = acc[i][1] + bv[1];
        v0.z = acc[i][2] + bv[2]; v0.w = acc[i][3] + bv[3];
        v1.x = acc[i][4] + bv[4]; v1.y = acc[i][5] + bv[5];
        v1.z = acc[i][6] + bv[6]; v1.w = acc[i][7] + bv[7];
        *(float4*)(cp)     = v0;
        *(float4*)(cp + 4) = v1;
    }
}

// ---------------------------------------------------------------------------
// Kernel 4: top-4 nearest neighbors by integer squared distance.
// Packed key = (sq << 11) | idx : ascending order == (dist, idx) lexicographic,
// which matches jax.lax.top_k's stable lower-index tie-break exactly.
// ---------------------------------------------------------------------------
__global__ void __launch_bounds__(256)
topk_kernel(const int* __restrict__ ca, const int* __restrict__ cb) {
    __shared__ unsigned sc[NB_];
    const int b = blockIdx.y;
    const int a = blockIdx.x * 256 + threadIdx.x;

    const int* cbb = cb + (size_t)b * NB_ * 3;
    for (int j = threadIdx.x; j < NB_; j += 256) {
        int x = cbb[j * 3 + 0];
        int y = cbb[j * 3 + 1];
        int z = cbb[j * 3 + 2];
        sc[j] = (unsigned)(x | (y << 8) | (z << 16));
    }
    __syncthreads();

    const int gi = b * NA_ + a;
    const int ax = ca[gi * 3 + 0];
    const int ay = ca[gi * 3 + 1];
    const int az = ca[gi * 3 + 2];

    unsigned k0 = 0xFFFFFFFFu, k1 = 0xFFFFFFFFu, k2 = 0xFFFFFFFFu, k3 = 0xFFFFFFFFu;

#pragma unroll 4
    for (int j = 0; j < NB_; ++j) {
        unsigned c = sc[j];
        int dx = ax - (int)(c & 255u);
        int dy = ay - (int)((c >> 8) & 255u);
        int dz = az - (int)(c >> 16);
        unsigned sq = (unsigned)(dx * dx + dy * dy + dz * dz);   // <= 48387
        unsigned key = (sq << 11) | (unsigned)j;
        if (key < k3) {
            k3 = key;
            unsigned t;
            if (k3 < k2) { t = k2; k2 = k3; k3 = t; }
            if (k2 < k1) { t = k1; k1 = k2; k2 = t; }
            if (k1 < k0) { t = k0; k0 = k1; k1 = t; }
        }
    }
    uint4 r; r.x = k0; r.y = k1; r.z = k2; r.w = k3;
    *(uint4*)&g_topk[(size_t)gi * 4] = r;
}

// ---------------------------------------------------------------------------
// Kernel 5: combine.
// out[token][0:512]   = feats_a[token]
// out[token][512:1024]= sum_k relu(Pa[token] + Pb[idx_k]) * w_k
// w_k = max(0.5 - sqrt(sq_k)/128, 0)
// ---------------------------------------------------------------------------
__global__ void __launch_bounds__(128)
combine_kernel(const float* __restrict__ feats_a, float* __restrict__ out) {
    const int token = blockIdx.x;          // 0..32767
    const int b     = token >> 11;         // batch
    const int tid   = threadIdx.x;         // 0..127, one float4 of channels

    uint4 keys = *(const uint4*)&g_topk[(size_t)token * 4];
    unsigned ks[4] = {keys.x, keys.y, keys.z, keys.w};
    float w[4];
    int   idx[4];
#pragma unroll
    for (int k = 0; k < 4; ++k) {
        idx[k] = (int)(ks[k] & 2047u);
        float d = sqrtf((float)(ks[k] >> 11)) * (1.0f / 128.0f);
        w[k] = fmaxf(0.5f - d, 0.0f);
    }

    const size_t rowOff = (size_t)token * D_ + tid * 4;
    float4 fa = *(const float4*)(feats_a + rowOff);
    float4 pa = *(const float4*)(g_Pa + rowOff);

    float4 acc; acc.x = acc.y = acc.z = acc.w = 0.0f;
    const size_t baseB = (size_t)b * NB_ * D_;
#pragma unroll
    for (int k = 0; k < 4; ++k) {
        float4 pb = *(const float4*)(g_Pb + baseB + (size_t)idx[k] * D_ + tid * 4);
        acc.x += fmaxf(pa.x + pb.x, 0.0f) * w[k];
        acc.y += fmaxf(pa.y + pb.y, 0.0f) * w[k];
        acc.z += fmaxf(pa.z + pb.z, 0.0f) * w[k];
        acc.w += fmaxf(pa.w + pb.w, 0.0f) * w[k];
    }

    float* orow = out + (size_t)token * (2 * D_);
    *(float4*)(orow + tid * 4)        = fa;
    *(float4*)(orow + D_ + tid * 4)   = acc;
}

// ---------------------------------------------------------------------------
// Launch. Inputs (metadata order): feats_a, feats_b, W, bias, coords_a, coords_b
// ---------------------------------------------------------------------------
extern "C" void kernel_launch(void* const* d_in, const int* in_sizes, int n_in,
                              void* d_out, int out_size) {
    const float* feats_a = (const float*)d_in[0];
    const float* feats_b = (const float*)d_in[1];
    const float* W       = (const float*)d_in[2];
    const float* bias    = (const float*)d_in[3];
    const int*   ca      = (const int*)d_in[4];
    const int*   cb      = (const int*)d_in[5];
    float*       out     = (float*)d_out;

    // 1) Wd = W1 - W2
    prep_wd_kernel<<<256, 256>>>(W);

    // 2) Pa = feats_a @ W2 + bias   (W2 = rows 512..1023 => offset 512*512)
    sgemm512_kernel<0><<<dim3(4, 256), 256>>>(feats_a, W + 512 * 512, bias);

    // 3) Pb = feats_b @ Wd
    sgemm512_kernel<1><<<dim3(4, 256), 256>>>(feats_b, nullptr, nullptr);

    // 4) top-4 neighbor keys
    topk_kernel<<<dim3(NA_ / 256, B_), 256>>>(ca, cb);

    // 5) combine + output assembly
    combine_kernel<<<M_, 128>>>(feats_a, out);

    (void)in_sizes; (void)n_in; (void)out_size;
}

// round 3
// speedup vs baseline: 2.0010x; 2.0010x over previous
#include <cuda_runtime.h>
#include <cuda_bf16.h>
#include <cstdint>

// Problem constants
#define B_   16
#define NA_  2048
#define NB_  2048
#define D_   512
#define M_   (B_ * NA_)      // 32768 tokens
#define TOPK_ 4

// Scratch (device globals: allocation-free per harness rules)
__device__ float    g_Pa[M_ * D_];            // feats_a @ W2 + bias     (64 MB)
__device__ float    g_Pb[M_ * D_];            // feats_b @ (W1 - W2)     (64 MB)
__device__ unsigned g_topk[M_ * TOPK_];       // packed keys (sq<<11|idx)
__device__ __nv_bfloat16 g_Bhi[2][D_ * D_];   // [mode][k*512+n]  hi part
__device__ __nv_bfloat16 g_Blo[2][D_ * D_];   // [mode][k*512+n]  lo part

// ===========================================================================
// PTX helpers (baseline PTX only — compiles under compute_103)
// ===========================================================================
__device__ __forceinline__ uint32_t smem_u32(const void* p) {
    uint32_t a;
    asm("{ .reg .u64 t; cvta.to.shared.u64 t, %1; cvt.u32.u64 %0, t; }"
        : "=r"(a) : "l"(p));
    return a;
}

__device__ __forceinline__ void ldsm4(uint32_t addr, uint32_t* r) {
    asm volatile("ldmatrix.sync.aligned.m8n8.x4.shared.b16 {%0,%1,%2,%3}, [%4];"
                 : "=r"(r[0]), "=r"(r[1]), "=r"(r[2]), "=r"(r[3]) : "r"(addr));
}
__device__ __forceinline__ void ldsm4t(uint32_t addr, uint32_t* r) {
    asm volatile("ldmatrix.sync.aligned.m8n8.x4.trans.shared.b16 {%0,%1,%2,%3}, [%4];"
                 : "=r"(r[0]), "=r"(r[1]), "=r"(r[2]), "=r"(r[3]) : "r"(addr));
}
__device__ __forceinline__ void mma16816(float* c, const uint32_t* a, const uint32_t* b) {
    asm volatile(
        "mma.sync.aligned.m16n8k16.row.col.f32.bf16.bf16.f32 "
        "{%0,%1,%2,%3}, {%4,%5,%6,%7}, {%8,%9}, {%0,%1,%2,%3};"
        : "+f"(c[0]), "+f"(c[1]), "+f"(c[2]), "+f"(c[3])
        : "r"(a[0]), "r"(a[1]), "r"(a[2]), "r"(a[3]), "r"(b[0]), "r"(b[1]));
}

// ===========================================================================
// Kernel 1: prep — bf16 hi/lo split of W2 and (W1 - W2), natural [k][n] layout.
// ===========================================================================
__global__ void prep_kernel(const float* __restrict__ W) {
    int idx = blockIdx.x * blockDim.x + threadIdx.x;   // k*512 + n
    float w1 = W[idx];
    float w2 = W[idx + 512 * 512];
    float v0 = w2;
    float v1 = w1 - w2;
    __nv_bfloat16 h0 = __float2bfloat16(v0);
    __nv_bfloat16 l0 = __float2bfloat16(v0 - __bfloat162float(h0));
    __nv_bfloat16 h1 = __float2bfloat16(v1);
    __nv_bfloat16 l1 = __float2bfloat16(v1 - __bfloat162float(h1));
    g_Bhi[0][idx] = h0;  g_Blo[0][idx] = l0;
    g_Bhi[1][idx] = h1;  g_Blo[1][idx] = l1;
}

// ===========================================================================
// Kernel 2/3: bf16-split tensor-core GEMM, C(M x 512) = A(M x 512) @ Bm + bias
// CTA tile 128x128, 8 warps (2x4), warp tile 64x32, K stage 32, double buffer.
// 3 passes: Ah*Bh + Ah*Bl + Al*Bh  (fp32 accum; lo*lo dropped ~2^-16)
// ===========================================================================
#define A_STRIDE 40                      // bf16 elems per A smem row (32+8 pad)
#define B_STRIDE 136                     // bf16 elems per B smem row (128+8 pad)
#define A_PART   (128 * A_STRIDE * 2)    // 10240 B
#define B_PART   (32 * B_STRIDE * 2)     // 8704 B
#define OFF_AH   0
#define OFF_AL   A_PART
#define OFF_BH   (2 * A_PART)
#define OFF_BL   (2 * A_PART + B_PART)
#define BUF_SZ   (2 * A_PART + 2 * B_PART)   // 37888 B
#define GEMM_SMEM (2 * BUF_SZ)               // 75776 B

template <int MODE>
__global__ void __launch_bounds__(256, 1)
mma_gemm(const float* __restrict__ A, const float* __restrict__ bias) {
    extern __shared__ char smem[];
    const uint32_t sb = smem_u32(smem);

    const int tid  = threadIdx.x;
    const int wid  = tid >> 5;
    const int lane = tid & 31;
    const int wm   = wid & 1;        // 0..1  (64-row slabs)
    const int wn   = wid >> 1;       // 0..3  (32-col slabs)
    const int bn   = blockIdx.x;     // 0..3
    const int bm   = blockIdx.y;     // 0..255

    const float* Ab = A + (size_t)bm * 128 * 512;
    const __nv_bfloat16* Bh = g_Bhi[MODE];
    const __nv_bfloat16* Bl = g_Blo[MODE];
    float* C = (MODE == 0) ? g_Pa : g_Pb;
    const int nb = bn * 128;

    // fill-index precompute
    const int arow = tid >> 1;             // 0..127
    const int acb  = (tid & 1) * 16;       // col base (16 cols per thread)

    // ldmatrix lane offsets
    const int r = lane & 7, q = lane >> 3;
    const uint32_t a_lane = (uint32_t)(((q & 1) * 8 + r) * A_STRIDE + (q >> 1) * 8);
    const uint32_t b_lane = (uint32_t)(((q & 1) * 8 + r) * B_STRIDE + (q >> 1) * 8);

    float c[4][4][4];
#pragma unroll
    for (int mi = 0; mi < 4; ++mi)
#pragma unroll
        for (int ni = 0; ni < 4; ++ni)
#pragma unroll
            for (int e = 0; e < 4; ++e) c[mi][ni][e] = 0.0f;

    // ---- stage fill helper (registers -> smem, with A fp32->bf16 split) ----
    auto store_stage = [&](int buf, const float4* a4, const uint4* bh4, const uint4* bl4) {
        char* bp = smem + buf * BUF_SZ;
#pragma unroll
        for (int i = 0; i < 4; ++i) {
            float4 v = a4[i];
            __nv_bfloat16 hx = __float2bfloat16(v.x);
            __nv_bfloat16 hy = __float2bfloat16(v.y);
            __nv_bfloat16 hz = __float2bfloat16(v.z);
            __nv_bfloat16 hw = __float2bfloat16(v.w);
            __nv_bfloat16 lx = __float2bfloat16(v.x - __bfloat162float(hx));
            __nv_bfloat16 ly = __float2bfloat16(v.y - __bfloat162float(hy));
            __nv_bfloat16 lz = __float2bfloat16(v.z - __bfloat162float(hz));
            __nv_bfloat16 lw = __float2bfloat16(v.w - __bfloat162float(hw));
            __nv_bfloat162 hp0(hx, hy), hp1(hz, hw), lp0(lx, ly), lp1(lz, lw);
            uint2 h2, l2;
            h2.x = *(const uint32_t*)&hp0;  h2.y = *(const uint32_t*)&hp1;
            l2.x = *(const uint32_t*)&lp0;  l2.y = *(const uint32_t*)&lp1;
            uint32_t off = (uint32_t)((arow * A_STRIDE + acb + i * 4) * 2);
            *(uint2*)(bp + OFF_AH + off) = h2;
            *(uint2*)(bp + OFF_AL + off) = l2;
        }
#pragma unroll
        for (int i = 0; i < 2; ++i) {
            int idx = tid * 2 + i;
            int brow = idx >> 4;             // 0..31
            int bcol = (idx & 15) * 8;       // 0..120
            uint32_t off = (uint32_t)((brow * B_STRIDE + bcol) * 2);
            *(uint4*)(bp + OFF_BH + off) = bh4[i];
            *(uint4*)(bp + OFF_BL + off) = bl4[i];
        }
    };
    auto load_stage = [&](int k0, float4* a4, uint4* bh4, uint4* bl4) {
        const float* ap = Ab + (size_t)arow * 512 + k0 + acb;
#pragma unroll
        for (int i = 0; i < 4; ++i) a4[i] = *(const float4*)(ap + i * 4);
#pragma unroll
        for (int i = 0; i < 2; ++i) {
            int idx = tid * 2 + i;
            int brow = idx >> 4;
            int bcol = (idx & 15) * 8;
            size_t g = (size_t)(k0 + brow) * 512 + nb + bcol;
            bh4[i] = *(const uint4*)(Bh + g);
            bl4[i] = *(const uint4*)(Bl + g);
        }
    };

    // prologue
    {
        float4 a4[4]; uint4 bh4[2], bl4[2];
        load_stage(0, a4, bh4, bl4);
        store_stage(0, a4, bh4, bl4);
    }
    __syncthreads();

    for (int s = 0; s < 16; ++s) {
        const int buf = s & 1;
        float4 a4[4]; uint4 bh4[2], bl4[2];
        if (s < 15) load_stage((s + 1) * 32, a4, bh4, bl4);

        const uint32_t bpu = sb + buf * BUF_SZ;
#pragma unroll
        for (int kc = 0; kc < 2; ++kc) {
            uint32_t ah[4][4], al[4][4], bhf[4][2], blf[4][2];
#pragma unroll
            for (int mi = 0; mi < 4; ++mi) {
                uint32_t aoff = (uint32_t)(((wm * 64 + mi * 16) * A_STRIDE + kc * 16) * 2) +
                                a_lane * 2;
                ldsm4(bpu + OFF_AH + aoff, ah[mi]);
                ldsm4(bpu + OFF_AL + aoff, al[mi]);
            }
#pragma unroll
            for (int np = 0; np < 2; ++np) {
                uint32_t boff = (uint32_t)((kc * 16 * B_STRIDE + wn * 32 + np * 16) * 2) +
                                b_lane * 2;
                uint32_t t[4];
                ldsm4t(bpu + OFF_BH + boff, t);
                bhf[np * 2][0] = t[0]; bhf[np * 2][1] = t[1];
                bhf[np * 2 + 1][0] = t[2]; bhf[np * 2 + 1][1] = t[3];
                ldsm4t(bpu + OFF_BL + boff, t);
                blf[np * 2][0] = t[0]; blf[np * 2][1] = t[1];
                blf[np * 2 + 1][0] = t[2]; blf[np * 2 + 1][1] = t[3];
            }
#pragma unroll
            for (int mi = 0; mi < 4; ++mi)
#pragma unroll
                for (int ni = 0; ni < 4; ++ni)
                    mma16816(c[mi][ni], ah[mi], bhf[ni]);
#pragma unroll
            for (int mi = 0; mi < 4; ++mi)
#pragma unroll
                for (int ni = 0; ni < 4; ++ni)
                    mma16816(c[mi][ni], ah[mi], blf[ni]);
#pragma unroll
            for (int mi = 0; mi < 4; ++mi)
#pragma unroll
                for (int ni = 0; ni < 4; ++ni)
                    mma16816(c[mi][ni], al[mi], bhf[ni]);
        }

        if (s < 15) {
            store_stage(buf ^ 1, a4, bh4, bl4);
            __syncthreads();
        }
    }

    // epilogue
    const int g   = lane >> 2;
    const int tig = lane & 3;
#pragma unroll
    for (int mi = 0; mi < 4; ++mi) {
        const size_t row0 = (size_t)bm * 128 + wm * 64 + mi * 16 + g;
#pragma unroll
        for (int ni = 0; ni < 4; ++ni) {
            const int colg = nb + wn * 32 + ni * 8 + tig * 2;
            float2 bv;
            if (MODE == 0) bv = *(const float2*)(bias + colg);
            else           { bv.x = 0.0f; bv.y = 0.0f; }
            float2 v0, v1;
            v0.x = c[mi][ni][0] + bv.x;  v0.y = c[mi][ni][1] + bv.y;
            v1.x = c[mi][ni][2] + bv.x;  v1.y = c[mi][ni][3] + bv.y;
            *(float2*)(C + row0 * 512 + colg)       = v0;
            *(float2*)(C + (row0 + 8) * 512 + colg) = v1;
        }
    }
}

// ===========================================================================
// Kernel 4: top-4 nearest neighbors (packed key sq<<11|idx; exact integer).
// ===========================================================================
__global__ void __launch_bounds__(128)
topk_kernel(const int* __restrict__ ca, const int* __restrict__ cb) {
    __shared__ unsigned sc[NB_];
    const int b = blockIdx.y;
    const int a = blockIdx.x * 128 + threadIdx.x;

    const int* cbb = cb + (size_t)b * NB_ * 3;
    for (int j = threadIdx.x; j < NB_; j += 128) {
        int x = cbb[j * 3 + 0];
        int y = cbb[j * 3 + 1];
        int z = cbb[j * 3 + 2];
        sc[j] = (unsigned)(x | (y << 8) | (z << 16));
    }
    __syncthreads();

    const int gi = b * NA_ + a;
    const unsigned ap = (unsigned)(ca[gi * 3 + 0] | (ca[gi * 3 + 1] << 8) |
                                   (ca[gi * 3 + 2] << 16));

    unsigned k0 = 0xFFFFFFFFu, k1 = 0xFFFFFFFFu, k2 = 0xFFFFFFFFu, k3 = 0xFFFFFFFFu;

#pragma unroll 4
    for (int j = 0; j < NB_; ++j) {
        unsigned d  = __vabsdiffu4(ap, sc[j]);
        unsigned sq = __dp4a(d, d, 0u);                  // <= 48387
        unsigned key = (sq << 11) | (unsigned)j;
        if (key < k3) {
            k3 = key;
            unsigned t;
            if (k3 < k2) { t = k2; k2 = k3; k3 = t; }
            if (k2 < k1) { t = k1; k1 = k2; k2 = t; }
            if (k1 < k0) { t = k0; k0 = k1; k1 = t; }
        }
    }
    uint4 rr; rr.x = k0; rr.y = k1; rr.z = k2; rr.w = k3;
    *(uint4*)&g_topk[(size_t)gi * 4] = rr;
}

// ===========================================================================
// Kernel 5: combine.
// out[t][0:512] = feats_a[t];  out[t][512:] = sum_k relu(Pa[t]+Pb[idx_k])*w_k
// ===========================================================================
__global__ void __launch_bounds__(128)
combine_kernel(const float* __restrict__ feats_a, float* __restrict__ out) {
    const int token = blockIdx.x;
    const int b     = token >> 11;
    const int tid   = threadIdx.x;

    uint4 keys = *(const uint4*)&g_topk[(size_t)token * 4];
    unsigned ks[4] = {keys.x, keys.y, keys.z, keys.w};
    float w[4];
    int   idx[4];
#pragma unroll
    for (int k = 0; k < 4; ++k) {
        idx[k] = (int)(ks[k] & 2047u);
        float d = sqrtf((float)(ks[k] >> 11)) * (1.0f / 128.0f);
        w[k] = fmaxf(0.5f - d, 0.0f);
    }

    const size_t rowOff = (size_t)token * D_ + tid * 4;
    float4 fa = *(const float4*)(feats_a + rowOff);
    float4 pa = *(const float4*)(g_Pa + rowOff);

    float4 acc; acc.x = acc.y = acc.z = acc.w = 0.0f;
    const size_t baseB = (size_t)b * NB_ * D_;
#pragma unroll
    for (int k = 0; k < 4; ++k) {
        float4 pb = *(const float4*)(g_Pb + baseB + (size_t)idx[k] * D_ + tid * 4);
        acc.x += fmaxf(pa.x + pb.x, 0.0f) * w[k];
        acc.y += fmaxf(pa.y + pb.y, 0.0f) * w[k];
        acc.z += fmaxf(pa.z + pb.z, 0.0f) * w[k];
        acc.w += fmaxf(pa.w + pb.w, 0.0f) * w[k];
    }

    float* orow = out + (size_t)token * (2 * D_);
    *(float4*)(orow + tid * 4)      = fa;
    *(float4*)(orow + D_ + tid * 4) = acc;
}

// ===========================================================================
// Launch. Inputs: feats_a, feats_b, W, bias, coords_a, coords_b
// ===========================================================================
extern "C" void kernel_launch(void* const* d_in, const int* in_sizes, int n_in,
                              void* d_out, int out_size) {
    const float* feats_a = (const float*)d_in[0];
    const float* feats_b = (const float*)d_in[1];
    const float* W       = (const float*)d_in[2];
    const float* bias    = (const float*)d_in[3];
    const int*   ca      = (const int*)d_in[4];
    const int*   cb      = (const int*)d_in[5];
    float*       out     = (float*)d_out;

    // opt-in >48KB dynamic smem (host-side attribute; not a stream op)
    static bool attr_done = false;
    if (!attr_done) {
        cudaFuncSetAttribute(mma_gemm<0>, cudaFuncAttributeMaxDynamicSharedMemorySize,
                             GEMM_SMEM);
        cudaFuncSetAttribute(mma_gemm<1>, cudaFuncAttributeMaxDynamicSharedMemorySize,
                             GEMM_SMEM);
        attr_done = true;
    }

    // 1) bf16 split of W2 and (W1 - W2), [k][n] layout
    prep_kernel<<<1024, 256>>>(W);

    // 2) Pa = feats_a @ W2 + bias
    mma_gemm<0><<<dim3(4, 256), 256, GEMM_SMEM>>>(feats_a, bias);

    // 3) Pb = feats_b @ (W1 - W2)
    mma_gemm<1><<<dim3(4, 256), 256, GEMM_SMEM>>>(feats_b, nullptr);

    // 4) top-4 neighbor keys
    topk_kernel<<<dim3(NA_ / 128, B_), 128>>>(ca, cb);

    // 5) combine + output assembly
    combine_kernel<<<M_, 128>>>(feats_a, out);

    (void)in_sizes; (void)n_in; (void)out_size;
}